// round 8
// baseline (speedup 1.0000x reference)
#include <cuda_runtime.h>
#include <cstdint>

// ---------------- problem constants ----------------
#define TOK   16384
#define DIMD  1024
#define FF    4096
#define NEXP  8
#define TM    128
#define TN    128
#define KT    32
#define ROW_TILES 264
#define R_CAP (ROW_TILES*TM)     // 33792
#define KSPLIT 2                 // gemm2 split-k

// smem (floats): 3 stages of A(4096) + B(4352); 2 CTAs/SM
#define A_STAGE 4096
#define B_STAGE 4352             // 32 k-rows x 136 (128 + 8 pad)
#define NSTAGE  3
#define SMEM_FLOATS (NSTAGE*(A_STAGE+B_STAGE))
#define SMEM_BYTES  (SMEM_FLOATS*4 + 1024)   // + sTok/sGate tables

// ---------------- device scratch ----------------
__device__ float g_xg[(size_t)R_CAP * DIMD];            // gathered x, tf32-rounded
__device__ float g_h[(size_t)R_CAP * FF];               // hidden, tf32-rounded
__device__ float g_w1r[(size_t)NEXP * DIMD * FF];       // tf32-rounded W1 [e][d][f]
__device__ float g_w2r[(size_t)NEXP * FF * DIMD];       // tf32-rounded W2 [e][f][d]

__device__ int   g_row_token[R_CAP];
__device__ float g_row_gate[R_CAP];
__device__ int   g_tok_e[TOK * 2];
__device__ float g_tok_g[TOK * 2];
__device__ int   g_counts[NEXP];
__device__ int   g_off[NEXP + 1];
__device__ int   g_cursor[NEXP];

// ---------------- helpers ----------------
__device__ __forceinline__ uint32_t smem_u32(const void* p) {
    uint32_t a;
    asm("{ .reg .u64 t; cvta.to.shared.u64 t, %1; cvt.u32.u64 %0, t; }" : "=r"(a) : "l"(p));
    return a;
}
__device__ __forceinline__ void cp_async16(uint32_t dst, const void* src) {
    asm volatile("cp.async.cg.shared.global [%0], [%1], 16;" :: "r"(dst), "l"(src));
}
#define CP_COMMIT() asm volatile("cp.async.commit_group;" ::: "memory")
#define CP_WAIT1()  asm volatile("cp.async.wait_group 1;" ::: "memory")
#define CP_WAIT0()  asm volatile("cp.async.wait_group 0;" ::: "memory")

__device__ __forceinline__ float to_tf32(float x) {
    uint32_t r;
    asm("cvt.rna.tf32.f32 %0, %1;" : "=r"(r) : "f"(x));
    return __uint_as_float(r);
}
__device__ __forceinline__ void mma_tf32(float* d,
    uint32_t a0, uint32_t a1, uint32_t a2, uint32_t a3,
    uint32_t b0, uint32_t b1) {
    asm volatile("mma.sync.aligned.m16n8k8.row.col.f32.tf32.tf32.f32 "
        "{%0,%1,%2,%3}, {%4,%5,%6,%7}, {%8,%9}, {%0,%1,%2,%3};"
        : "+f"(d[0]), "+f"(d[1]), "+f"(d[2]), "+f"(d[3])
        : "r"(a0), "r"(a1), "r"(a2), "r"(a3), "r"(b0), "r"(b1));
}

// ---------------- routing kernels ----------------
__global__ void init_kernel() {
    int i = blockIdx.x * 256 + threadIdx.x;
    if (i < NEXP) g_counts[i] = 0;
    if (i < R_CAP) { g_row_token[i] = 0; g_row_gate[i] = 0.f; }
}

__global__ __launch_bounds__(256) void router_kernel(const float* __restrict__ x,
                                                     const float* __restrict__ Wg) {
    __shared__ float sWg[NEXP * DIMD];
    int tid = threadIdx.x;
    for (int i = tid; i < NEXP * DIMD; i += 256) {
        int d = i & (DIMD - 1);
        int e = i >> 10;
        sWg[i] = Wg[d * NEXP + e];
    }
    __syncthreads();
    int warp = tid >> 5, lane = tid & 31;
    int token = blockIdx.x * 8 + warp;
    const float* xr = x + (size_t)token * DIMD;
    float acc[NEXP];
#pragma unroll
    for (int e = 0; e < NEXP; e++) acc[e] = 0.f;
    for (int d = lane; d < DIMD; d += 32) {
        float xv = xr[d];
#pragma unroll
        for (int e = 0; e < NEXP; e++) acc[e] = fmaf(xv, sWg[e * DIMD + d], acc[e]);
    }
#pragma unroll
    for (int e = 0; e < NEXP; e++)
#pragma unroll
        for (int o = 16; o; o >>= 1) acc[e] += __shfl_xor_sync(0xFFFFFFFFu, acc[e], o);
    if (lane == 0) {
        int e0 = 0; float l0 = acc[0];
#pragma unroll
        for (int e = 1; e < NEXP; e++) if (acc[e] > l0) { l0 = acc[e]; e0 = e; }
        int e1 = -1; float l1 = -3.4e38f;
#pragma unroll
        for (int e = 0; e < NEXP; e++) if (e != e0 && acc[e] > l1) { l1 = acc[e]; e1 = e; }
        float g0 = 1.f / (1.f + expf(l1 - l0));
        g_tok_e[token * 2 + 0] = e0;
        g_tok_e[token * 2 + 1] = e1;
        g_tok_g[token * 2 + 0] = g0;
        g_tok_g[token * 2 + 1] = 1.f - g0;
        atomicAdd(&g_counts[e0], 1);
        atomicAdd(&g_counts[e1], 1);
    }
}

__global__ void scan_kernel() {
    if (threadIdx.x == 0) {
        int off = 0;
        for (int e = 0; e < NEXP; e++) {
            g_off[e] = off;
            g_cursor[e] = off;
            off += ((g_counts[e] + TM - 1) / TM) * TM;
        }
        g_off[NEXP] = off;
    }
}

__global__ void assign_kernel() {
    int t = blockIdx.x * 256 + threadIdx.x;
    if (t >= TOK) return;
#pragma unroll
    for (int k = 0; k < 2; k++) {
        int e = g_tok_e[t * 2 + k];
        int p = atomicAdd(&g_cursor[e], 1);
        g_row_token[p] = t;
        g_row_gate[p] = g_tok_g[t * 2 + k];
    }
}

// gather x rows (padded segments), round to tf32
__global__ __launch_bounds__(256) void gather_x_kernel(const float* __restrict__ x) {
    size_t base = ((size_t)blockIdx.x * 256 + threadIdx.x) * 4;
    int row = (int)(base >> 10);
    int col = (int)(base & 1023);
    int tok = g_row_token[row];
    float4 v = *(const float4*)(x + (size_t)tok * DIMD + col);
    v.x = to_tf32(v.x); v.y = to_tf32(v.y); v.z = to_tf32(v.z); v.w = to_tf32(v.w);
    *(float4*)(g_xg + base) = v;
}

// elementwise tf32 rounding for weights
__global__ __launch_bounds__(256) void round_w_kernel(const float* __restrict__ src,
                                                      float* __restrict__ dst) {
    size_t i = ((size_t)blockIdx.x * 256 + threadIdx.x) * 4;
    float4 v = *(const float4*)(src + i);
    v.x = to_tf32(v.x); v.y = to_tf32(v.y); v.z = to_tf32(v.z); v.w = to_tf32(v.w);
    *(float4*)(dst + i) = v;
}

// pre-fill out[t] = g0*b2[e0] + g1*b2[e1]  (gemm2 atomically adds g*y on top)
__global__ __launch_bounds__(256) void init_out_kernel(const float* __restrict__ b2,
                                                       float* __restrict__ out) {
    int t = blockIdx.x;
    int d = threadIdx.x * 4;
    int e0 = g_tok_e[t * 2], e1 = g_tok_e[t * 2 + 1];
    float gg0 = g_tok_g[t * 2], gg1 = g_tok_g[t * 2 + 1];
    float4 bA = *(const float4*)(b2 + (size_t)e0 * DIMD + d);
    float4 bB = *(const float4*)(b2 + (size_t)e1 * DIMD + d);
    float4 o;
    o.x = gg0 * bA.x + gg1 * bB.x;
    o.y = gg0 * bA.y + gg1 * bB.y;
    o.z = gg0 * bA.z + gg1 * bB.z;
    o.w = gg0 * bA.w + gg1 * bB.w;
    *(float4*)(out + (size_t)t * DIMD + d) = o;
}

// ---------------- tf32 mma mainloop (TM=128, TN=128, 8 warps 2x4, warp tile 64x32) ----------------
struct Frag { float acc[4][4][4]; };

__device__ __forceinline__ void load_tile(float* As, float* Bs, int s, int kt,
                                          const float* Agm, int lda,
                                          const float* Bgm, int ldb, int tid) {
#pragma unroll
    for (int i = 0; i < 4; i++) {           // A: 128 rows x 32 floats = 1024 chunks
        int c = tid + i * 256;
        int r = c >> 3, ch = c & 7;
        uint32_t dst = smem_u32(&As[s * A_STAGE + r * 32 + ((ch ^ (r & 7)) << 2)]);
        cp_async16(dst, Agm + (size_t)r * lda + kt * KT + ch * 4);
    }
#pragma unroll
    for (int i = 0; i < 4; i++) {           // B: 32 k-rows x 128 floats = 1024 chunks
        int c = tid + i * 256;
        int kr = c >> 5, ch = c & 31;
        uint32_t dst = smem_u32(&Bs[s * B_STAGE + kr * 136 + ch * 4]);
        cp_async16(dst, Bgm + (size_t)(kt * KT + kr) * ldb + ch * 4);
    }
}

__device__ __forceinline__ void gemm_mainloop(Frag& F, float* As, float* Bs,
                                              const float* Agm, int lda,
                                              const float* Bgm, int ldb,
                                              int ktiles, int tid) {
    int lane = tid & 31, wid = tid >> 5;
    int warp_m = wid & 1, warp_n = wid >> 1;
    int gid = lane >> 2, tig = lane & 3;

    int arow[4], bcol[4];
#pragma unroll
    for (int mt = 0; mt < 4; mt++) arow[mt] = (warp_m * 64 + mt * 16 + gid) * 32 + tig;
#pragma unroll
    for (int nt = 0; nt < 4; nt++) bcol[nt] = warp_n * 32 + nt * 8 + gid;

#pragma unroll
    for (int mt = 0; mt < 4; mt++)
#pragma unroll
        for (int nt = 0; nt < 4; nt++)
#pragma unroll
            for (int q = 0; q < 4; q++) F.acc[mt][nt][q] = 0.f;

    load_tile(As, Bs, 0, 0, Agm, lda, Bgm, ldb, tid); CP_COMMIT();
    load_tile(As, Bs, 1, 1, Agm, lda, Bgm, ldb, tid); CP_COMMIT();

    for (int kt = 0; kt < ktiles; kt++) {
        int s = kt % 3;
        CP_WAIT1();
        __syncthreads();
        int ktn = kt + 2;
        if (ktn < ktiles)
            load_tile(As, Bs, ktn % 3, ktn, Agm, lda, Bgm, ldb, tid);
        CP_COMMIT();

        const float* as = As + s * A_STAGE;
        const float* bs = Bs + s * B_STAGE;
#pragma unroll
        for (int ks = 0; ks < 4; ks++) {
            int ax = ((2 * ks) ^ gid) << 2;
            uint32_t af[4][4];
#pragma unroll
            for (int mt = 0; mt < 4; mt++) {
                af[mt][0] = __float_as_uint(as[arow[mt] + ax]);
                af[mt][1] = __float_as_uint(as[arow[mt] + ax + 256]);
                af[mt][2] = __float_as_uint(as[arow[mt] + (ax ^ 4)]);
                af[mt][3] = __float_as_uint(as[arow[mt] + (ax ^ 4) + 256]);
            }
            int kb0 = (8 * ks + tig) * 136;
            uint32_t bf[4][2];
#pragma unroll
            for (int nt = 0; nt < 4; nt++) {
                bf[nt][0] = __float_as_uint(bs[kb0 + bcol[nt]]);
                bf[nt][1] = __float_as_uint(bs[kb0 + 4 * 136 + bcol[nt]]);
            }
#pragma unroll
            for (int mt = 0; mt < 4; mt++)
#pragma unroll
                for (int nt = 0; nt < 4; nt++)
                    mma_tf32(F.acc[mt][nt], af[mt][0], af[mt][1], af[mt][2], af[mt][3],
                             bf[nt][0], bf[nt][1]);
        }
    }
    CP_WAIT0();
}

// ---------------- GEMM1: h = tf32(relu(g_xg @ W1r[e] + b1[e])) ----------------
// bid.x = row*2 + n_lo (row-fastest, N-pairs co-resident), bid.y = n_hi
__global__ __launch_bounds__(256, 2) void gemm1_kernel(const float* __restrict__ b1) {
    extern __shared__ float sm[];
    float* As = sm;
    float* Bs = sm + NSTAGE * A_STAGE;
    int tid = threadIdx.x;
    int row0 = (blockIdx.x >> 1) * TM;
    int n0 = (blockIdx.y * 2 + (blockIdx.x & 1)) * TN;
    int e = 0;
#pragma unroll
    for (int i = 1; i < NEXP; i++) e += (row0 >= g_off[i]) ? 1 : 0;

    const float* Agm = g_xg + (size_t)row0 * DIMD;
    const float* Bgm = g_w1r + (size_t)e * DIMD * FF + n0;

    Frag F;
    gemm_mainloop(F, As, Bs, Agm, DIMD, Bgm, FF, DIMD / KT, tid);

    int lane = tid & 31, wid = tid >> 5;
    int warp_m = wid & 1, warp_n = wid >> 1;
    int gid = lane >> 2, tig = lane & 3;
    const float* bias = b1 + e * FF + n0;

#pragma unroll
    for (int nt = 0; nt < 4; nt++) {
        int gc = warp_n * 32 + nt * 8 + tig * 2;
        float bv0 = __ldg(bias + gc), bv1 = __ldg(bias + gc + 1);
#pragma unroll
        for (int mt = 0; mt < 4; mt++) {
            int gr0 = row0 + warp_m * 64 + mt * 16 + gid;
            float2 v0, v1;
            v0.x = to_tf32(fmaxf(F.acc[mt][nt][0] + bv0, 0.f));
            v0.y = to_tf32(fmaxf(F.acc[mt][nt][1] + bv1, 0.f));
            v1.x = to_tf32(fmaxf(F.acc[mt][nt][2] + bv0, 0.f));
            v1.y = to_tf32(fmaxf(F.acc[mt][nt][3] + bv1, 0.f));
            *(float2*)(g_h + (size_t)gr0 * FF + n0 + gc) = v0;
            *(float2*)(g_h + (size_t)(gr0 + 8) * FF + n0 + gc) = v1;
        }
    }
}

// ---------------- GEMM2: out[token] += gate * (h @ W2r[e]) with split-k ----------------
// bid.x = row*2 + n_lo, bid.y = n_hi*KSPLIT + kslice
__global__ __launch_bounds__(256, 2) void gemm2_kernel(float* __restrict__ out) {
    extern __shared__ float sm[];
    float* As = sm;
    float* Bs = sm + NSTAGE * A_STAGE;
    int* sTok = (int*)(sm + SMEM_FLOATS);
    float* sGate = (float*)(sm + SMEM_FLOATS + 128);
    int tid = threadIdx.x;
    int row0 = (blockIdx.x >> 1) * TM;
    int nq = blockIdx.y >> 1;          // n_hi (0..1)
    int ksl = blockIdx.y & 1;          // k slice (0..1)
    int n0 = (nq * 2 + (blockIdx.x & 1)) * TN;   // wait: DIMD/TN = 8 N tiles; pairs -> 4 n_hi
    // NOTE: grid.y = (DIMD/(TN*2)) * KSPLIT = 4*2 = 8; decode n_hi in [0,4):
    nq = blockIdx.y >> 1;              // 0..3
    n0 = (nq * 2 + (blockIdx.x & 1)) * TN;
    int e = 0;
#pragma unroll
    for (int i = 1; i < NEXP; i++) e += (row0 >= g_off[i]) ? 1 : 0;

    if (tid < TM) {
        sTok[tid] = g_row_token[row0 + tid];
        sGate[tid] = g_row_gate[row0 + tid];
    }
    __syncthreads();

    const int khalf = FF / KSPLIT;     // 2048
    const float* Agm = g_h + (size_t)row0 * FF + (size_t)ksl * khalf;
    const float* Bgm = g_w2r + (size_t)e * FF * DIMD + (size_t)ksl * khalf * DIMD + n0;

    Frag F;
    gemm_mainloop(F, As, Bs, Agm, FF, Bgm, DIMD, khalf / KT, tid);

    int lane = tid & 31, wid = tid >> 5;
    int warp_m = wid & 1, warp_n = wid >> 1;
    int gid = lane >> 2, tig = lane & 3;

#pragma unroll
    for (int nt = 0; nt < 4; nt++) {
        int gc = warp_n * 32 + nt * 8 + tig * 2;
#pragma unroll
        for (int mt = 0; mt < 4; mt++) {
            int lr0 = warp_m * 64 + mt * 16 + gid;
            int t0 = sTok[lr0], t1 = sTok[lr0 + 8];
            float ga = sGate[lr0], gb = sGate[lr0 + 8];
            float* o0 = out + (size_t)t0 * DIMD + n0 + gc;
            float* o1 = out + (size_t)t1 * DIMD + n0 + gc;
            atomicAdd(o0,     ga * F.acc[mt][nt][0]);
            atomicAdd(o0 + 1, ga * F.acc[mt][nt][1]);
            atomicAdd(o1,     gb * F.acc[mt][nt][2]);
            atomicAdd(o1 + 1, gb * F.acc[mt][nt][3]);
        }
    }
}

// ---------------- host launch ----------------
extern "C" void kernel_launch(void* const* d_in, const int* in_sizes, int n_in,
                              void* d_out, int out_size) {
    const float* x  = (const float*)d_in[0];
    const float* Wg = (const float*)d_in[1];
    const float* W1 = (const float*)d_in[2];
    const float* b1 = (const float*)d_in[3];
    const float* W2 = (const float*)d_in[4];
    const float* b2 = (const float*)d_in[5];
    float* out = (float*)d_out;

    cudaFuncSetAttribute(gemm1_kernel, cudaFuncAttributeMaxDynamicSharedMemorySize, SMEM_BYTES);
    cudaFuncSetAttribute(gemm2_kernel, cudaFuncAttributeMaxDynamicSharedMemorySize, SMEM_BYTES);

    float *pW1r, *pW2r;
    cudaGetSymbolAddress((void**)&pW1r, g_w1r);
    cudaGetSymbolAddress((void**)&pW2r, g_w2r);

    init_kernel<<<R_CAP / 256, 256>>>();
    router_kernel<<<TOK / 8, 256>>>(x, Wg);
    scan_kernel<<<1, 32>>>();
    assign_kernel<<<TOK / 256, 256>>>();
    gather_x_kernel<<<(R_CAP * (DIMD / 4)) / 256, 256>>>(x);
    round_w_kernel<<<(NEXP * DIMD * FF / 4) / 256, 256>>>(W1, pW1r);
    round_w_kernel<<<(NEXP * FF * DIMD / 4) / 256, 256>>>(W2, pW2r);
    init_out_kernel<<<TOK, 256>>>(b2, out);
    gemm1_kernel<<<dim3(ROW_TILES * 2, FF / (TN * 2)), 256, SMEM_BYTES>>>(b1);
    gemm2_kernel<<<dim3(ROW_TILES * 2, (DIMD / (TN * 2)) * KSPLIT), 256, SMEM_BYTES>>>(out);
}

// round 9
// speedup vs baseline: 1.0071x; 1.0071x over previous
#include <cuda_runtime.h>
#include <cstdint>

// ---------------- problem constants ----------------
#define TOK   16384
#define DIMD  1024
#define FF    4096
#define NEXP  8
#define TM    128
#define TN    128
#define KT    32
#define ROW_TILES 264
#define R_CAP (ROW_TILES*TM)     // 33792
#define KSPLIT 2                 // gemm2 split-k (non-atomic, partial slabs)

// smem (floats): 3 stages of A(4096) + B(4352); 2 CTAs/SM
#define A_STAGE 4096
#define B_STAGE 4352             // 32 k-rows x 136 (128 + 8 pad)
#define NSTAGE  3
#define SMEM_FLOATS (NSTAGE*(A_STAGE+B_STAGE))
#define SMEM_BYTES  (SMEM_FLOATS*4 + 512)   // + sTok table

// ---------------- device scratch ----------------
__device__ float g_xr[(size_t)TOK * DIMD];              // x rounded to tf32 (token order)
__device__ float g_h[(size_t)R_CAP * FF];               // hidden, tf32-rounded
__device__ float g_y2[(size_t)KSPLIT * R_CAP * DIMD];   // gemm2 split-k partials
__device__ float g_w1r[(size_t)NEXP * DIMD * FF];       // tf32-rounded W1 [e][d][f]
__device__ float g_w2r[(size_t)NEXP * FF * DIMD];       // tf32-rounded W2 [e][f][d]

__device__ int   g_row_token[R_CAP];
__device__ int   g_tok_e[TOK * 2];
__device__ float g_tok_g[TOK * 2];
__device__ int   g_tok_row[TOK * 2];
__device__ int   g_counts[NEXP];
__device__ int   g_off[NEXP + 1];
__device__ int   g_cursor[NEXP];

// ---------------- helpers ----------------
__device__ __forceinline__ uint32_t smem_u32(const void* p) {
    uint32_t a;
    asm("{ .reg .u64 t; cvta.to.shared.u64 t, %1; cvt.u32.u64 %0, t; }" : "=r"(a) : "l"(p));
    return a;
}
__device__ __forceinline__ void cp_async16(uint32_t dst, const void* src) {
    asm volatile("cp.async.cg.shared.global [%0], [%1], 16;" :: "r"(dst), "l"(src));
}
#define CP_COMMIT() asm volatile("cp.async.commit_group;" ::: "memory")
#define CP_WAIT1()  asm volatile("cp.async.wait_group 1;" ::: "memory")
#define CP_WAIT0()  asm volatile("cp.async.wait_group 0;" ::: "memory")

__device__ __forceinline__ float to_tf32(float x) {
    uint32_t r;
    asm("cvt.rna.tf32.f32 %0, %1;" : "=r"(r) : "f"(x));
    return __uint_as_float(r);
}
__device__ __forceinline__ void mma_tf32(float* d,
    uint32_t a0, uint32_t a1, uint32_t a2, uint32_t a3,
    uint32_t b0, uint32_t b1) {
    asm volatile("mma.sync.aligned.m16n8k8.row.col.f32.tf32.tf32.f32 "
        "{%0,%1,%2,%3}, {%4,%5,%6,%7}, {%8,%9}, {%0,%1,%2,%3};"
        : "+f"(d[0]), "+f"(d[1]), "+f"(d[2]), "+f"(d[3])
        : "r"(a0), "r"(a1), "r"(a2), "r"(a3), "r"(b0), "r"(b1));
}

// ---------------- routing kernels ----------------
__global__ void init_kernel() {
    int i = blockIdx.x * 256 + threadIdx.x;
    if (i < NEXP) g_counts[i] = 0;
    if (i < R_CAP) g_row_token[i] = 0;
}

__global__ __launch_bounds__(256) void router_kernel(const float* __restrict__ x,
                                                     const float* __restrict__ Wg) {
    __shared__ float sWg[NEXP * DIMD];
    int tid = threadIdx.x;
    for (int i = tid; i < NEXP * DIMD; i += 256) {
        int d = i & (DIMD - 1);
        int e = i >> 10;
        sWg[i] = Wg[d * NEXP + e];
    }
    __syncthreads();
    int warp = tid >> 5, lane = tid & 31;
    int token = blockIdx.x * 8 + warp;
    const float* xr = x + (size_t)token * DIMD;
    float acc[NEXP];
#pragma unroll
    for (int e = 0; e < NEXP; e++) acc[e] = 0.f;
    for (int d = lane; d < DIMD; d += 32) {
        float xv = xr[d];
#pragma unroll
        for (int e = 0; e < NEXP; e++) acc[e] = fmaf(xv, sWg[e * DIMD + d], acc[e]);
    }
#pragma unroll
    for (int e = 0; e < NEXP; e++)
#pragma unroll
        for (int o = 16; o; o >>= 1) acc[e] += __shfl_xor_sync(0xFFFFFFFFu, acc[e], o);
    if (lane == 0) {
        int e0 = 0; float l0 = acc[0];
#pragma unroll
        for (int e = 1; e < NEXP; e++) if (acc[e] > l0) { l0 = acc[e]; e0 = e; }
        int e1 = -1; float l1 = -3.4e38f;
#pragma unroll
        for (int e = 0; e < NEXP; e++) if (e != e0 && acc[e] > l1) { l1 = acc[e]; e1 = e; }
        float g0 = 1.f / (1.f + expf(l1 - l0));
        g_tok_e[token * 2 + 0] = e0;
        g_tok_e[token * 2 + 1] = e1;
        g_tok_g[token * 2 + 0] = g0;
        g_tok_g[token * 2 + 1] = 1.f - g0;
        atomicAdd(&g_counts[e0], 1);
        atomicAdd(&g_counts[e1], 1);
    }
}

__global__ void scan_kernel() {
    if (threadIdx.x == 0) {
        int off = 0;
        for (int e = 0; e < NEXP; e++) {
            g_off[e] = off;
            g_cursor[e] = off;
            off += ((g_counts[e] + TM - 1) / TM) * TM;
        }
        g_off[NEXP] = off;
    }
}

__global__ void assign_kernel() {
    int t = blockIdx.x * 256 + threadIdx.x;
    if (t >= TOK) return;
#pragma unroll
    for (int k = 0; k < 2; k++) {
        int e = g_tok_e[t * 2 + k];
        int p = atomicAdd(&g_cursor[e], 1);
        g_row_token[p] = t;
        g_tok_row[t * 2 + k] = p;
    }
}

// round x to tf32 in token order (gemm1 gathers rows at cp.async time)
__global__ __launch_bounds__(256) void round_x_kernel(const float* __restrict__ x) {
    size_t i = ((size_t)blockIdx.x * 256 + threadIdx.x) * 4;
    float4 v = *(const float4*)(x + i);
    v.x = to_tf32(v.x); v.y = to_tf32(v.y); v.z = to_tf32(v.z); v.w = to_tf32(v.w);
    *(float4*)(g_xr + i) = v;
}

// elementwise tf32 rounding for weights
__global__ __launch_bounds__(256) void round_w_kernel(const float* __restrict__ src,
                                                      float* __restrict__ dst) {
    size_t i = ((size_t)blockIdx.x * 256 + threadIdx.x) * 4;
    float4 v = *(const float4*)(src + i);
    v.x = to_tf32(v.x); v.y = to_tf32(v.y); v.z = to_tf32(v.z); v.w = to_tf32(v.w);
    *(float4*)(dst + i) = v;
}

// ---------------- tf32 mma mainloop (TM=128, TN=128, 8 warps 2x4, warp tile 64x32) ----------------
struct Frag { float acc[4][4][4]; };

// GATHER: A rows indirected through sTok (outside the inner loop; cp.async issue only)
template<bool GATHER>
__device__ __forceinline__ void load_tile(float* As, float* Bs, const int* sTok,
                                          int s, int kt,
                                          const float* Agm, int lda,
                                          const float* Bgm, int ldb, int tid) {
#pragma unroll
    for (int i = 0; i < 4; i++) {           // A: 128 rows x 32 floats = 1024 chunks
        int c = tid + i * 256;
        int r = c >> 3, ch = c & 7;
        uint32_t dst = smem_u32(&As[s * A_STAGE + r * 32 + ((ch ^ (r & 7)) << 2)]);
        size_t row = GATHER ? (size_t)sTok[r] : (size_t)r;
        cp_async16(dst, Agm + row * lda + kt * KT + ch * 4);
    }
#pragma unroll
    for (int i = 0; i < 4; i++) {           // B: 32 k-rows x 128 floats = 1024 chunks
        int c = tid + i * 256;
        int kr = c >> 5, ch = c & 31;
        uint32_t dst = smem_u32(&Bs[s * B_STAGE + kr * 136 + ch * 4]);
        cp_async16(dst, Bgm + (size_t)(kt * KT + kr) * ldb + ch * 4);
    }
}

template<bool GATHER>
__device__ __forceinline__ void gemm_mainloop(Frag& F, float* As, float* Bs, const int* sTok,
                                              const float* Agm, int lda,
                                              const float* Bgm, int ldb,
                                              int ktiles, int tid) {
    int lane = tid & 31, wid = tid >> 5;
    int warp_m = wid & 1, warp_n = wid >> 1;
    int gid = lane >> 2, tig = lane & 3;

    int arow[4], bcol[4];
#pragma unroll
    for (int mt = 0; mt < 4; mt++) arow[mt] = (warp_m * 64 + mt * 16 + gid) * 32 + tig;
#pragma unroll
    for (int nt = 0; nt < 4; nt++) bcol[nt] = warp_n * 32 + nt * 8 + gid;

#pragma unroll
    for (int mt = 0; mt < 4; mt++)
#pragma unroll
        for (int nt = 0; nt < 4; nt++)
#pragma unroll
            for (int q = 0; q < 4; q++) F.acc[mt][nt][q] = 0.f;

    load_tile<GATHER>(As, Bs, sTok, 0, 0, Agm, lda, Bgm, ldb, tid); CP_COMMIT();
    load_tile<GATHER>(As, Bs, sTok, 1, 1, Agm, lda, Bgm, ldb, tid); CP_COMMIT();

    for (int kt = 0; kt < ktiles; kt++) {
        int s = kt % 3;
        CP_WAIT1();
        __syncthreads();
        int ktn = kt + 2;
        if (ktn < ktiles)
            load_tile<GATHER>(As, Bs, sTok, ktn % 3, ktn, Agm, lda, Bgm, ldb, tid);
        CP_COMMIT();

        const float* as = As + s * A_STAGE;
        const float* bs = Bs + s * B_STAGE;
#pragma unroll
        for (int ks = 0; ks < 4; ks++) {
            int ax = ((2 * ks) ^ gid) << 2;
            uint32_t af[4][4];
#pragma unroll
            for (int mt = 0; mt < 4; mt++) {
                af[mt][0] = __float_as_uint(as[arow[mt] + ax]);
                af[mt][1] = __float_as_uint(as[arow[mt] + ax + 256]);
                af[mt][2] = __float_as_uint(as[arow[mt] + (ax ^ 4)]);
                af[mt][3] = __float_as_uint(as[arow[mt] + (ax ^ 4) + 256]);
            }
            int kb0 = (8 * ks + tig) * 136;
            uint32_t bf[4][2];
#pragma unroll
            for (int nt = 0; nt < 4; nt++) {
                bf[nt][0] = __float_as_uint(bs[kb0 + bcol[nt]]);
                bf[nt][1] = __float_as_uint(bs[kb0 + 4 * 136 + bcol[nt]]);
            }
#pragma unroll
            for (int mt = 0; mt < 4; mt++)
#pragma unroll
                for (int nt = 0; nt < 4; nt++)
                    mma_tf32(F.acc[mt][nt], af[mt][0], af[mt][1], af[mt][2], af[mt][3],
                             bf[nt][0], bf[nt][1]);
        }
    }
    CP_WAIT0();
}

// ---------------- GEMM1: h = tf32(relu(gather(g_xr) @ W1r[e] + b1[e])) ----------------
// bid.x = row*2 + n_lo (row-fastest, N-pairs co-resident), bid.y = n_hi
__global__ __launch_bounds__(256, 2) void gemm1_kernel(const float* __restrict__ b1) {
    extern __shared__ float sm[];
    float* As = sm;
    float* Bs = sm + NSTAGE * A_STAGE;
    int* sTok = (int*)(sm + SMEM_FLOATS);
    int tid = threadIdx.x;
    int row0 = (blockIdx.x >> 1) * TM;
    int n0 = (blockIdx.y * 2 + (blockIdx.x & 1)) * TN;
    int e = 0;
#pragma unroll
    for (int i = 1; i < NEXP; i++) e += (row0 >= g_off[i]) ? 1 : 0;

    if (tid < TM) sTok[tid] = g_row_token[row0 + tid];
    __syncthreads();

    const float* Bgm = g_w1r + (size_t)e * DIMD * FF + n0;

    Frag F;
    gemm_mainloop<true>(F, As, Bs, sTok, g_xr, DIMD, Bgm, FF, DIMD / KT, tid);

    int lane = tid & 31, wid = tid >> 5;
    int warp_m = wid & 1, warp_n = wid >> 1;
    int gid = lane >> 2, tig = lane & 3;
    const float* bias = b1 + e * FF + n0;

#pragma unroll
    for (int nt = 0; nt < 4; nt++) {
        int gc = warp_n * 32 + nt * 8 + tig * 2;
        float bv0 = __ldg(bias + gc), bv1 = __ldg(bias + gc + 1);
#pragma unroll
        for (int mt = 0; mt < 4; mt++) {
            int gr0 = row0 + warp_m * 64 + mt * 16 + gid;
            float2 v0, v1;
            v0.x = to_tf32(fmaxf(F.acc[mt][nt][0] + bv0, 0.f));
            v0.y = to_tf32(fmaxf(F.acc[mt][nt][1] + bv1, 0.f));
            v1.x = to_tf32(fmaxf(F.acc[mt][nt][2] + bv0, 0.f));
            v1.y = to_tf32(fmaxf(F.acc[mt][nt][3] + bv1, 0.f));
            *(float2*)(g_h + (size_t)gr0 * FF + n0 + gc) = v0;
            *(float2*)(g_h + (size_t)(gr0 + 8) * FF + n0 + gc) = v1;
        }
    }
}

// ---------------- GEMM2: y2[ksl] = h[:, ksl*2048:(ksl+1)*2048] @ W2r[e] slice ----------------
// bid.x = row*2 + n_lo, bid.y = n_hi*2 + kslice  (grid.y = 4*KSPLIT = 8)
__global__ __launch_bounds__(256, 2) void gemm2_kernel() {
    extern __shared__ float sm[];
    float* As = sm;
    float* Bs = sm + NSTAGE * A_STAGE;
    int tid = threadIdx.x;
    int row0 = (blockIdx.x >> 1) * TM;
    int nq = blockIdx.y >> 1;          // n_hi in [0,4)
    int ksl = blockIdx.y & 1;          // k slice in [0,2)
    int n0 = (nq * 2 + (blockIdx.x & 1)) * TN;
    int e = 0;
#pragma unroll
    for (int i = 1; i < NEXP; i++) e += (row0 >= g_off[i]) ? 1 : 0;

    const int khalf = FF / KSPLIT;     // 2048
    const float* Agm = g_h + (size_t)row0 * FF + (size_t)ksl * khalf;
    const float* Bgm = g_w2r + (size_t)e * FF * DIMD + (size_t)ksl * khalf * DIMD + n0;
    float* yslice = g_y2 + (size_t)ksl * R_CAP * DIMD;

    Frag F;
    gemm_mainloop<false>(F, As, Bs, nullptr, Agm, FF, Bgm, DIMD, khalf / KT, tid);

    int lane = tid & 31, wid = tid >> 5;
    int warp_m = wid & 1, warp_n = wid >> 1;
    int gid = lane >> 2, tig = lane & 3;

#pragma unroll
    for (int nt = 0; nt < 4; nt++) {
        int gc = warp_n * 32 + nt * 8 + tig * 2;
#pragma unroll
        for (int mt = 0; mt < 4; mt++) {
            int gr0 = row0 + warp_m * 64 + mt * 16 + gid;
            float2 v0 = { F.acc[mt][nt][0], F.acc[mt][nt][1] };
            float2 v1 = { F.acc[mt][nt][2], F.acc[mt][nt][3] };
            *(float2*)(yslice + (size_t)gr0 * DIMD + n0 + gc) = v0;
            *(float2*)(yslice + (size_t)(gr0 + 8) * DIMD + n0 + gc) = v1;
        }
    }
}

// ---------------- combine: out[t] = sum_k g_k*(y0[row_k]+y1[row_k] + b2[e_k]) ----------------
__global__ __launch_bounds__(256) void combine_kernel(const float* __restrict__ b2,
                                                      float* __restrict__ out) {
    int t = blockIdx.x;
    int d = threadIdx.x * 4;
    int r0 = g_tok_row[t * 2], r1 = g_tok_row[t * 2 + 1];
    int e0 = g_tok_e[t * 2],   e1 = g_tok_e[t * 2 + 1];
    float gg0 = g_tok_g[t * 2], gg1 = g_tok_g[t * 2 + 1];
    const float* y0a = g_y2 + (size_t)r0 * DIMD + d;
    const float* y0b = y0a + (size_t)R_CAP * DIMD;
    const float* y1a = g_y2 + (size_t)r1 * DIMD + d;
    const float* y1b = y1a + (size_t)R_CAP * DIMD;
    float4 p0 = *(const float4*)y0a, q0 = *(const float4*)y0b;
    float4 p1 = *(const float4*)y1a, q1 = *(const float4*)y1b;
    float4 bA = *(const float4*)(b2 + (size_t)e0 * DIMD + d);
    float4 bB = *(const float4*)(b2 + (size_t)e1 * DIMD + d);
    float4 o;
    o.x = gg0 * (p0.x + q0.x + bA.x) + gg1 * (p1.x + q1.x + bB.x);
    o.y = gg0 * (p0.y + q0.y + bA.y) + gg1 * (p1.y + q1.y + bB.y);
    o.z = gg0 * (p0.z + q0.z + bA.z) + gg1 * (p1.z + q1.z + bB.z);
    o.w = gg0 * (p0.w + q0.w + bA.w) + gg1 * (p1.w + q1.w + bB.w);
    *(float4*)(out + (size_t)t * DIMD + d) = o;
}

// ---------------- host launch ----------------
extern "C" void kernel_launch(void* const* d_in, const int* in_sizes, int n_in,
                              void* d_out, int out_size) {
    const float* x  = (const float*)d_in[0];
    const float* Wg = (const float*)d_in[1];
    const float* W1 = (const float*)d_in[2];
    const float* b1 = (const float*)d_in[3];
    const float* W2 = (const float*)d_in[4];
    const float* b2 = (const float*)d_in[5];
    float* out = (float*)d_out;

    cudaFuncSetAttribute(gemm1_kernel, cudaFuncAttributeMaxDynamicSharedMemorySize, SMEM_BYTES);
    cudaFuncSetAttribute(gemm2_kernel, cudaFuncAttributeMaxDynamicSharedMemorySize, SMEM_BYTES);

    float *pW1r, *pW2r;
    cudaGetSymbolAddress((void**)&pW1r, g_w1r);
    cudaGetSymbolAddress((void**)&pW2r, g_w2r);

    init_kernel<<<R_CAP / 256, 256>>>();
    router_kernel<<<TOK / 8, 256>>>(x, Wg);
    scan_kernel<<<1, 32>>>();
    assign_kernel<<<TOK / 256, 256>>>();
    round_x_kernel<<<(TOK * (DIMD / 4)) / 256, 256>>>(x);
    round_w_kernel<<<(NEXP * DIMD * FF / 4) / 256, 256>>>(W1, pW1r);
    round_w_kernel<<<(NEXP * FF * DIMD / 4) / 256, 256>>>(W2, pW2r);
    gemm1_kernel<<<dim3(ROW_TILES * 2, FF / (TN * 2)), 256, SMEM_BYTES>>>(b1);
    gemm2_kernel<<<dim3(ROW_TILES * 2, (DIMD / (TN * 2)) * KSPLIT), 256, SMEM_BYTES>>>();
    combine_kernel<<<TOK, 256>>>(b2, out);
}

// round 10
// speedup vs baseline: 1.0440x; 1.0366x over previous
#include <cuda_runtime.h>
#include <cstdint>

// ---------------- problem constants ----------------
#define TOK   16384
#define DIMD  1024
#define FF    4096
#define NEXP  8
#define TM    128
#define TN    128
#define KT    32
#define ROW_TILES 264
#define R_CAP (ROW_TILES*TM)     // 33792

// smem (floats): 3 stages of A(4096) + B(4352); 2 CTAs/SM
#define A_STAGE 4096
#define B_STAGE 4352             // 32 k-rows x 136 (128 + 8 pad)
#define NSTAGE  3
#define SMEM_FLOATS (NSTAGE*(A_STAGE+B_STAGE))
#define SMEM_BYTES  (SMEM_FLOATS*4)

// prep kernel block ranges (each block: 256 threads x float4 = 1024 floats)
#define PREP_G1 (R_CAP*DIMD/1024)            // 33792 gather+round x
#define PREP_G2 (NEXP*DIMD*FF/1024)          // 32768 round W1
#define PREP_G3 (NEXP*FF*DIMD/1024)          // 32768 round W2

// ---------------- device scratch ----------------
__device__ float g_xg[(size_t)R_CAP * DIMD];            // gathered x, tf32-rounded
__device__ float g_h[(size_t)R_CAP * FF];               // hidden, tf32-rounded
__device__ float g_y[(size_t)R_CAP * DIMD];             // gemm2 raw output
__device__ float g_w1r[(size_t)NEXP * DIMD * FF];       // tf32-rounded W1 [e][d][f]
__device__ float g_w2r[(size_t)NEXP * FF * DIMD];       // tf32-rounded W2 [e][f][d]

__device__ int   g_row_token[R_CAP];
__device__ int   g_tok_e[TOK * 2];
__device__ float g_tok_g[TOK * 2];
__device__ int   g_tok_row[TOK * 2];
__device__ int   g_counts[NEXP];
__device__ int   g_off[NEXP + 1];
__device__ int   g_cursor[NEXP];

// ---------------- helpers ----------------
__device__ __forceinline__ uint32_t smem_u32(const void* p) {
    uint32_t a;
    asm("{ .reg .u64 t; cvta.to.shared.u64 t, %1; cvt.u32.u64 %0, t; }" : "=r"(a) : "l"(p));
    return a;
}
__device__ __forceinline__ void cp_async16(uint32_t dst, const void* src) {
    asm volatile("cp.async.cg.shared.global [%0], [%1], 16;" :: "r"(dst), "l"(src));
}
#define CP_COMMIT() asm volatile("cp.async.commit_group;" ::: "memory")
#define CP_WAIT1()  asm volatile("cp.async.wait_group 1;" ::: "memory")
#define CP_WAIT0()  asm volatile("cp.async.wait_group 0;" ::: "memory")

__device__ __forceinline__ float to_tf32(float x) {
    uint32_t r;
    asm("cvt.rna.tf32.f32 %0, %1;" : "=r"(r) : "f"(x));
    return __uint_as_float(r);
}
__device__ __forceinline__ void mma_tf32(float* d,
    uint32_t a0, uint32_t a1, uint32_t a2, uint32_t a3,
    uint32_t b0, uint32_t b1) {
    asm volatile("mma.sync.aligned.m16n8k8.row.col.f32.tf32.tf32.f32 "
        "{%0,%1,%2,%3}, {%4,%5,%6,%7}, {%8,%9}, {%0,%1,%2,%3};"
        : "+f"(d[0]), "+f"(d[1]), "+f"(d[2]), "+f"(d[3])
        : "r"(a0), "r"(a1), "r"(a2), "r"(a3), "r"(b0), "r"(b1));
}

// ---------------- routing kernels ----------------
__global__ void init_kernel() {
    int i = blockIdx.x * 256 + threadIdx.x;
    if (i < NEXP) g_counts[i] = 0;
    if (i < R_CAP) g_row_token[i] = 0;
}

__global__ __launch_bounds__(256) void router_kernel(const float* __restrict__ x,
                                                     const float* __restrict__ Wg) {
    __shared__ float sWg[NEXP * DIMD];
    int tid = threadIdx.x;
    for (int i = tid; i < NEXP * DIMD; i += 256) {
        int d = i & (DIMD - 1);
        int e = i >> 10;
        sWg[i] = Wg[d * NEXP + e];
    }
    __syncthreads();
    int warp = tid >> 5, lane = tid & 31;
    int token = blockIdx.x * 8 + warp;
    const float* xr = x + (size_t)token * DIMD;
    float acc[NEXP];
#pragma unroll
    for (int e = 0; e < NEXP; e++) acc[e] = 0.f;
    for (int d = lane; d < DIMD; d += 32) {
        float xv = xr[d];
#pragma unroll
        for (int e = 0; e < NEXP; e++) acc[e] = fmaf(xv, sWg[e * DIMD + d], acc[e]);
    }
#pragma unroll
    for (int e = 0; e < NEXP; e++)
#pragma unroll
        for (int o = 16; o; o >>= 1) acc[e] += __shfl_xor_sync(0xFFFFFFFFu, acc[e], o);
    if (lane == 0) {
        int e0 = 0; float l0 = acc[0];
#pragma unroll
        for (int e = 1; e < NEXP; e++) if (acc[e] > l0) { l0 = acc[e]; e0 = e; }
        int e1 = -1; float l1 = -3.4e38f;
#pragma unroll
        for (int e = 0; e < NEXP; e++) if (e != e0 && acc[e] > l1) { l1 = acc[e]; e1 = e; }
        float g0 = 1.f / (1.f + expf(l1 - l0));
        g_tok_e[token * 2 + 0] = e0;
        g_tok_e[token * 2 + 1] = e1;
        g_tok_g[token * 2 + 0] = g0;
        g_tok_g[token * 2 + 1] = 1.f - g0;
        atomicAdd(&g_counts[e0], 1);
        atomicAdd(&g_counts[e1], 1);
    }
}

__global__ void scan_kernel() {
    if (threadIdx.x == 0) {
        int off = 0;
        for (int e = 0; e < NEXP; e++) {
            g_off[e] = off;
            g_cursor[e] = off;
            off += ((g_counts[e] + TM - 1) / TM) * TM;
        }
        g_off[NEXP] = off;
    }
}

__global__ void assign_kernel() {
    int t = blockIdx.x * 256 + threadIdx.x;
    if (t >= TOK) return;
#pragma unroll
    for (int k = 0; k < 2; k++) {
        int e = g_tok_e[t * 2 + k];
        int p = atomicAdd(&g_cursor[e], 1);
        g_row_token[p] = t;
        g_tok_row[t * 2 + k] = p;
    }
}

// ---------------- fused prep: gather+round x  |  round W1  |  round W2 ----------------
__global__ __launch_bounds__(256) void prep_kernel(const float* __restrict__ x,
                                                   const float* __restrict__ W1,
                                                   const float* __restrict__ W2) {
    int b = blockIdx.x;
    if (b < PREP_G1) {
        size_t base = ((size_t)b * 256 + threadIdx.x) * 4;
        int row = (int)(base >> 10);
        int col = (int)(base & 1023);
        int tok = g_row_token[row];
        float4 v = *(const float4*)(x + (size_t)tok * DIMD + col);
        v.x = to_tf32(v.x); v.y = to_tf32(v.y); v.z = to_tf32(v.z); v.w = to_tf32(v.w);
        *(float4*)(g_xg + base) = v;
    } else if (b < PREP_G1 + PREP_G2) {
        size_t i = ((size_t)(b - PREP_G1) * 256 + threadIdx.x) * 4;
        float4 v = *(const float4*)(W1 + i);
        v.x = to_tf32(v.x); v.y = to_tf32(v.y); v.z = to_tf32(v.z); v.w = to_tf32(v.w);
        *(float4*)(g_w1r + i) = v;
    } else {
        size_t i = ((size_t)(b - PREP_G1 - PREP_G2) * 256 + threadIdx.x) * 4;
        float4 v = *(const float4*)(W2 + i);
        v.x = to_tf32(v.x); v.y = to_tf32(v.y); v.z = to_tf32(v.z); v.w = to_tf32(v.w);
        *(float4*)(g_w2r + i) = v;
    }
}

// ---------------- tf32 mma mainloop (TM=128, TN=128, 8 warps 2x4, warp tile 64x32) ----------------
struct Frag { float acc[4][4][4]; };

__device__ __forceinline__ void load_tile(float* As, float* Bs, int s, int kt,
                                          const float* Agm, int lda,
                                          const float* Bgm, int ldb, int tid) {
#pragma unroll
    for (int i = 0; i < 4; i++) {           // A: 128 rows x 32 floats = 1024 chunks
        int c = tid + i * 256;
        int r = c >> 3, ch = c & 7;
        uint32_t dst = smem_u32(&As[s * A_STAGE + r * 32 + ((ch ^ (r & 7)) << 2)]);
        cp_async16(dst, Agm + (size_t)r * lda + kt * KT + ch * 4);
    }
#pragma unroll
    for (int i = 0; i < 4; i++) {           // B: 32 k-rows x 128 floats = 1024 chunks
        int c = tid + i * 256;
        int kr = c >> 5, ch = c & 31;
        uint32_t dst = smem_u32(&Bs[s * B_STAGE + kr * 136 + ch * 4]);
        cp_async16(dst, Bgm + (size_t)(kt * KT + kr) * ldb + ch * 4);
    }
}

__device__ __forceinline__ void gemm_mainloop(Frag& F, float* As, float* Bs,
                                              const float* Agm, int lda,
                                              const float* Bgm, int ldb,
                                              int ktiles, int tid) {
    int lane = tid & 31, wid = tid >> 5;
    int warp_m = wid & 1, warp_n = wid >> 1;
    int gid = lane >> 2, tig = lane & 3;

    int arow[4], bcol[4];
#pragma unroll
    for (int mt = 0; mt < 4; mt++) arow[mt] = (warp_m * 64 + mt * 16 + gid) * 32 + tig;
#pragma unroll
    for (int nt = 0; nt < 4; nt++) bcol[nt] = warp_n * 32 + nt * 8 + gid;

#pragma unroll
    for (int mt = 0; mt < 4; mt++)
#pragma unroll
        for (int nt = 0; nt < 4; nt++)
#pragma unroll
            for (int q = 0; q < 4; q++) F.acc[mt][nt][q] = 0.f;

    load_tile(As, Bs, 0, 0, Agm, lda, Bgm, ldb, tid); CP_COMMIT();
    load_tile(As, Bs, 1, 1, Agm, lda, Bgm, ldb, tid); CP_COMMIT();

    for (int kt = 0; kt < ktiles; kt++) {
        int s = kt % 3;
        CP_WAIT1();
        __syncthreads();
        int ktn = kt + 2;
        if (ktn < ktiles)
            load_tile(As, Bs, ktn % 3, ktn, Agm, lda, Bgm, ldb, tid);
        CP_COMMIT();

        const float* as = As + s * A_STAGE;
        const float* bs = Bs + s * B_STAGE;
#pragma unroll
        for (int ks = 0; ks < 4; ks++) {
            int ax = ((2 * ks) ^ gid) << 2;
            uint32_t af[4][4];
#pragma unroll
            for (int mt = 0; mt < 4; mt++) {
                af[mt][0] = __float_as_uint(as[arow[mt] + ax]);
                af[mt][1] = __float_as_uint(as[arow[mt] + ax + 256]);
                af[mt][2] = __float_as_uint(as[arow[mt] + (ax ^ 4)]);
                af[mt][3] = __float_as_uint(as[arow[mt] + (ax ^ 4) + 256]);
            }
            int kb0 = (8 * ks + tig) * 136;
            uint32_t bf[4][2];
#pragma unroll
            for (int nt = 0; nt < 4; nt++) {
                bf[nt][0] = __float_as_uint(bs[kb0 + bcol[nt]]);
                bf[nt][1] = __float_as_uint(bs[kb0 + 4 * 136 + bcol[nt]]);
            }
#pragma unroll
            for (int mt = 0; mt < 4; mt++)
#pragma unroll
                for (int nt = 0; nt < 4; nt++)
                    mma_tf32(F.acc[mt][nt], af[mt][0], af[mt][1], af[mt][2], af[mt][3],
                             bf[nt][0], bf[nt][1]);
        }
    }
    CP_WAIT0();
}

// ---------------- GEMM1: h = tf32(relu(g_xg @ W1r[e] + b1[e])) ----------------
// bid.x = row*2 + n_lo (row-fastest, N-pairs co-resident), bid.y = n_hi
__global__ __launch_bounds__(256, 2) void gemm1_kernel(const float* __restrict__ b1) {
    extern __shared__ float sm[];
    float* As = sm;
    float* Bs = sm + NSTAGE * A_STAGE;
    int tid = threadIdx.x;
    int row0 = (blockIdx.x >> 1) * TM;
    if (row0 >= g_off[NEXP]) return;           // skip unused capacity tiles
    int n0 = (blockIdx.y * 2 + (blockIdx.x & 1)) * TN;
    int e = 0;
#pragma unroll
    for (int i = 1; i < NEXP; i++) e += (row0 >= g_off[i]) ? 1 : 0;

    const float* Agm = g_xg + (size_t)row0 * DIMD;
    const float* Bgm = g_w1r + (size_t)e * DIMD * FF + n0;

    Frag F;
    gemm_mainloop(F, As, Bs, Agm, DIMD, Bgm, FF, DIMD / KT, tid);

    int lane = tid & 31, wid = tid >> 5;
    int warp_m = wid & 1, warp_n = wid >> 1;
    int gid = lane >> 2, tig = lane & 3;
    const float* bias = b1 + e * FF + n0;

#pragma unroll
    for (int nt = 0; nt < 4; nt++) {
        int gc = warp_n * 32 + nt * 8 + tig * 2;
        float bv0 = __ldg(bias + gc), bv1 = __ldg(bias + gc + 1);
#pragma unroll
        for (int mt = 0; mt < 4; mt++) {
            int gr0 = row0 + warp_m * 64 + mt * 16 + gid;
            float2 v0, v1;
            v0.x = to_tf32(fmaxf(F.acc[mt][nt][0] + bv0, 0.f));
            v0.y = to_tf32(fmaxf(F.acc[mt][nt][1] + bv1, 0.f));
            v1.x = to_tf32(fmaxf(F.acc[mt][nt][2] + bv0, 0.f));
            v1.y = to_tf32(fmaxf(F.acc[mt][nt][3] + bv1, 0.f));
            *(float2*)(g_h + (size_t)gr0 * FF + n0 + gc) = v0;
            *(float2*)(g_h + (size_t)(gr0 + 8) * FF + n0 + gc) = v1;
        }
    }
}

// ---------------- GEMM2: y = h @ W2r[e]  (bias+gate applied in combine) ----------------
__global__ __launch_bounds__(256, 2) void gemm2_kernel() {
    extern __shared__ float sm[];
    float* As = sm;
    float* Bs = sm + NSTAGE * A_STAGE;
    int tid = threadIdx.x;
    int row0 = (blockIdx.x >> 1) * TM;
    if (row0 >= g_off[NEXP]) return;           // skip unused capacity tiles
    int n0 = (blockIdx.y * 2 + (blockIdx.x & 1)) * TN;
    int e = 0;
#pragma unroll
    for (int i = 1; i < NEXP; i++) e += (row0 >= g_off[i]) ? 1 : 0;

    const float* Agm = g_h + (size_t)row0 * FF;
    const float* Bgm = g_w2r + (size_t)e * FF * DIMD + n0;

    Frag F;
    gemm_mainloop(F, As, Bs, Agm, FF, Bgm, DIMD, FF / KT, tid);

    int lane = tid & 31, wid = tid >> 5;
    int warp_m = wid & 1, warp_n = wid >> 1;
    int gid = lane >> 2, tig = lane & 3;

#pragma unroll
    for (int nt = 0; nt < 4; nt++) {
        int gc = warp_n * 32 + nt * 8 + tig * 2;
#pragma unroll
        for (int mt = 0; mt < 4; mt++) {
            int gr0 = row0 + warp_m * 64 + mt * 16 + gid;
            float2 v0 = { F.acc[mt][nt][0], F.acc[mt][nt][1] };
            float2 v1 = { F.acc[mt][nt][2], F.acc[mt][nt][3] };
            *(float2*)(g_y + (size_t)gr0 * DIMD + n0 + gc) = v0;
            *(float2*)(g_y + (size_t)(gr0 + 8) * DIMD + n0 + gc) = v1;
        }
    }
}

// ---------------- combine: out[t] = sum_k g_k*(y[row_k] + b2[e_k]) ----------------
__global__ __launch_bounds__(256) void combine_kernel(const float* __restrict__ b2,
                                                      float* __restrict__ out) {
    int t = blockIdx.x;
    int d = threadIdx.x * 4;
    int r0 = g_tok_row[t * 2], r1 = g_tok_row[t * 2 + 1];
    int e0 = g_tok_e[t * 2],   e1 = g_tok_e[t * 2 + 1];
    float gg0 = g_tok_g[t * 2], gg1 = g_tok_g[t * 2 + 1];
    float4 y0 = *(const float4*)(g_y + (size_t)r0 * DIMD + d);
    float4 y1 = *(const float4*)(g_y + (size_t)r1 * DIMD + d);
    float4 bA = *(const float4*)(b2 + (size_t)e0 * DIMD + d);
    float4 bB = *(const float4*)(b2 + (size_t)e1 * DIMD + d);
    float4 o;
    o.x = gg0 * (y0.x + bA.x) + gg1 * (y1.x + bB.x);
    o.y = gg0 * (y0.y + bA.y) + gg1 * (y1.y + bB.y);
    o.z = gg0 * (y0.z + bA.z) + gg1 * (y1.z + bB.z);
    o.w = gg0 * (y0.w + bA.w) + gg1 * (y1.w + bB.w);
    *(float4*)(out + (size_t)t * DIMD + d) = o;
}

// ---------------- host launch ----------------
extern "C" void kernel_launch(void* const* d_in, const int* in_sizes, int n_in,
                              void* d_out, int out_size) {
    const float* x  = (const float*)d_in[0];
    const float* Wg = (const float*)d_in[1];
    const float* W1 = (const float*)d_in[2];
    const float* b1 = (const float*)d_in[3];
    const float* W2 = (const float*)d_in[4];
    const float* b2 = (const float*)d_in[5];
    float* out = (float*)d_out;

    cudaFuncSetAttribute(gemm1_kernel, cudaFuncAttributeMaxDynamicSharedMemorySize, SMEM_BYTES);
    cudaFuncSetAttribute(gemm2_kernel, cudaFuncAttributeMaxDynamicSharedMemorySize, SMEM_BYTES);

    init_kernel<<<R_CAP / 256, 256>>>();                               // 1
    router_kernel<<<TOK / 8, 256>>>(x, Wg);                            // 2
    scan_kernel<<<1, 32>>>();                                          // 3
    assign_kernel<<<TOK / 256, 256>>>();                               // 4
    prep_kernel<<<PREP_G1 + PREP_G2 + PREP_G3, 256>>>(x, W1, W2);      // 5
    gemm1_kernel<<<dim3(ROW_TILES * 2, FF / (TN * 2)), 256, SMEM_BYTES>>>(b1);   // 6 <- ncu
    gemm2_kernel<<<dim3(ROW_TILES * 2, DIMD / (TN * 2)), 256, SMEM_BYTES>>>();   // 7
    combine_kernel<<<TOK, 256>>>(b2, out);                             // 8
}